// round 2
// baseline (speedup 1.0000x reference)
#include <cuda_runtime.h>
#include <math.h>

#define NN 110
#define H1_ 5
#define F1_ 24
#define HF 120          // H1*F1
#define H2_ 3
#define F2_ 3
#define XH_STRIDE 129   // padded stride for Xm/h1 buffer (odd-ish -> conflict free row gathers)
#define ATT_STRIDE 113  // padded stride for attention matrix
#define NEGV -9e15f
#define ALPHA 0.2f
#define NTHREADS 256

__device__ __forceinline__ float lrelu(float v) { return v > 0.f ? v : ALPHA * v; }
__device__ __forceinline__ float sigm(float v) { return 1.f / (1.f + __expf(-v)); }

__device__ __forceinline__ float warp_max(float v) {
#pragma unroll
    for (int o = 16; o > 0; o >>= 1) v = fmaxf(v, __shfl_xor_sync(0xffffffffu, v, o));
    return v;
}
__device__ __forceinline__ float warp_sum(float v) {
#pragma unroll
    for (int o = 16; o > 0; o >>= 1) v += __shfl_xor_sync(0xffffffffu, v, o);
    return v;
}

// Shared memory layout (floats)
// Xh   : NN*XH_STRIDE = 14190   (Xm, later h1 [n][h*24+f])
// feats: H1*NN*F1     = 13200
// uni  : 13200                  (W1s [i][120] in phase 1; attn [n][113] later)
// es1/en1: 550 each ; rinv: 110
// as1s/an1s: 120 each ; b1s: 24
// W2s: 1080 ; as2s/an2s: 9 each ; b2s: 3 ; fc1s: 3
// f2s: 3*110*4 = 1320 ; es2/en2: 330 each ; hacc: 440 ; ts: 110 ; us: 110
#define SMEM_FLOATS (14190 + 13200 + 13200 + 550 + 550 + 110 + 120 + 120 + 24 + 1080 + 9 + 9 + 3 + 3 + 1320 + 330 + 330 + 440 + 110 + 110)
#define SMEM_BYTES (SMEM_FLOATS * 4)

__global__ __launch_bounds__(NTHREADS, 1)
void gatmil_kernel(const float* __restrict__ X, const float* __restrict__ A,
                   const float* __restrict__ M,
                   const float* __restrict__ W1, const float* __restrict__ as1,
                   const float* __restrict__ an1, const float* __restrict__ b1,
                   const float* __restrict__ W2, const float* __restrict__ as2,
                   const float* __restrict__ an2, const float* __restrict__ b2,
                   const float* __restrict__ fc1, const float* __restrict__ fc2,
                   float* __restrict__ out)
{
    extern __shared__ float sm[];
    float* Xh    = sm;                       // 14190
    float* feats = Xh + NN * XH_STRIDE;      // 13200
    float* uni   = feats + H1_ * NN * F1_;   // 13200
    float* es1   = uni + 13200;              // 550
    float* en1   = es1 + H1_ * NN;           // 550
    float* rinv  = en1 + H1_ * NN;           // 110
    float* as1s  = rinv + NN;                // 120
    float* an1s  = as1s + HF;                // 120
    float* b1s   = an1s + HF;                // 24
    float* W2s   = b1s + F1_;                // 1080
    float* as2s  = W2s + H2_ * HF * F2_;     // 9
    float* an2s  = as2s + 9;                 // 9
    float* b2s   = an2s + 9;                 // 3
    float* fc1s  = b2s + 3;                  // 3
    float* f2s   = fc1s + 3;                 // 1320 (feats2 [h2][n][4])
    float* es2   = f2s + H2_ * NN * 4;       // 330
    float* en2   = es2 + H2_ * NN;           // 330
    float* hacc  = en2 + H2_ * NN;           // 440
    float* ts    = hacc + NN * 4;            // 110
    float* us    = ts + NN;                  // 110

    const int b = blockIdx.x;
    const int tid = threadIdx.x;
    const int lane = tid & 31;
    const int wid = tid >> 5;

    const float* Xb = X + (size_t)b * NN * NN;
    const float* Ab = A + (size_t)b * NN * NN;

    // ---- Phase 0: stage weights + masked input ----
    for (int i = tid; i < HF; i += NTHREADS) { as1s[i] = as1[i]; an1s[i] = an1[i]; }
    if (tid < F1_) b1s[tid] = b1[tid];
    for (int i = tid; i < H2_ * HF * F2_; i += NTHREADS) W2s[i] = W2[i];
    if (tid < H2_ * F2_) { as2s[tid] = as2[tid]; an2s[tid] = an2[tid]; }
    if (tid < F2_) { b2s[tid] = b2[tid]; fc1s[tid] = fc1[tid]; }
    // W1 -> [i][h*24+f] layout
    for (int idx = tid; idx < NN * HF; idx += NTHREADS) {
        int i = idx / HF, col = idx - i * HF;
        int h = col / F1_, f = col - h * F1_;
        uni[idx] = W1[(h * NN + i) * F1_ + f];
    }
    // Xm = X * sigmoid(M)
    for (int idx = tid; idx < NN * NN; idx += NTHREADS) {
        int n = idx / NN, i = idx - n * NN;
        Xh[n * XH_STRIDE + i] = Xb[idx] * sigm(M[idx]);
    }
    __syncthreads();

    // ---- Phase 1: feats[h][n][f] = (Xm @ W1)  [110x110 @ 110x120] ----
    {
        const int rg = tid >> 3;     // 0..31
        const int cg = tid & 7;      // 0..7
        const int n0 = rg * 4;
        const int c0 = cg * 15;
        if (rg < 28) {
            float acc[4][15];
#pragma unroll
            for (int r = 0; r < 4; r++)
#pragma unroll
                for (int c = 0; c < 15; c++) acc[r][c] = 0.f;
            for (int i = 0; i < NN; i++) {
                float a0[4];
#pragma unroll
                for (int r = 0; r < 4; r++)
                    a0[r] = (n0 + r < NN) ? Xh[(n0 + r) * XH_STRIDE + i] : 0.f;
#pragma unroll
                for (int c = 0; c < 15; c++) {
                    float w = uni[i * HF + c0 + c];
#pragma unroll
                    for (int r = 0; r < 4; r++) acc[r][c] = fmaf(a0[r], w, acc[r][c]);
                }
            }
#pragma unroll
            for (int r = 0; r < 4; r++) {
                int n = n0 + r;
                if (n < NN) {
#pragma unroll
                    for (int c = 0; c < 15; c++) {
                        int col = c0 + c;
                        int h = col / F1_, f = col - h * F1_;
                        feats[(h * NN + n) * F1_ + f] = acc[r][c];
                    }
                }
            }
        }
    }
    __syncthreads();

    // ---- Phase 1b: attention logits e_s, e_n per (head, node) ----
    for (int idx = tid; idx < H1_ * NN; idx += NTHREADS) {
        int h = idx / NN, n = idx - h * NN;
        const float* fp = feats + (h * NN + n) * F1_;
        float ss = 0.f, sn = 0.f;
#pragma unroll
        for (int f = 0; f < F1_; f++) {
            float v = fp[f];
            ss = fmaf(v, as1s[h * F1_ + f], ss);
            sn = fmaf(v, an1s[h * F1_ + f], sn);
        }
        es1[idx] = ss;
        en1[idx] = sn;
    }
    __syncthreads();

    // ---- Phase 2: per-head attention + aggregation -> h1 in Xh ----
    for (int h = 0; h < H1_; h++) {
        // attention rows: masked leaky softmax (unnormalized exp stored; 1/sum in rinv)
        for (int n = wid; n < NN; n += 8) {
            const float es = es1[h * NN + n];
            const float* Arow = Ab + n * NN;
            float vmax = -3.4e38f;
            for (int m = lane; m < NN; m += 32) {
                float v = lrelu(es + en1[h * NN + m]);
                if (Arow[m] <= 0.f) v = NEGV;
                uni[n * ATT_STRIDE + m] = v;
                vmax = fmaxf(vmax, v);
            }
            vmax = warp_max(vmax);
            float s = 0.f;
            for (int m = lane; m < NN; m += 32) {
                float ev = __expf(uni[n * ATT_STRIDE + m] - vmax);
                uni[n * ATT_STRIDE + m] = ev;
                s += ev;
            }
            s = warp_sum(s);
            if (lane == 0) rinv[n] = 1.f / s;
        }
        __syncthreads();
        // aggregation GEMM: h1[n][h*24+f] = lrelu( (attn_unnorm @ feats_h)[n][f]*rinv[n] + b1[f] )
        {
            const int rg = tid >> 3;   // 0..31
            const int cg = tid & 7;    // 0..7
            const int n0 = rg * 4;
            const int f0 = cg * 3;
            if (rg < 28) {
                float acc[4][3];
#pragma unroll
                for (int r = 0; r < 4; r++)
#pragma unroll
                    for (int c = 0; c < 3; c++) acc[r][c] = 0.f;
                for (int m = 0; m < NN; m++) {
                    float a0[4];
#pragma unroll
                    for (int r = 0; r < 4; r++)
                        a0[r] = (n0 + r < NN) ? uni[(n0 + r) * ATT_STRIDE + m] : 0.f;
#pragma unroll
                    for (int c = 0; c < 3; c++) {
                        float w = feats[(h * NN + m) * F1_ + f0 + c];
#pragma unroll
                        for (int r = 0; r < 4; r++) acc[r][c] = fmaf(a0[r], w, acc[r][c]);
                    }
                }
#pragma unroll
                for (int r = 0; r < 4; r++) {
                    int n = n0 + r;
                    if (n < NN) {
                        float ri = rinv[n];
#pragma unroll
                        for (int c = 0; c < 3; c++) {
                            int f = f0 + c;
                            Xh[n * XH_STRIDE + h * F1_ + f] = lrelu(fmaf(acc[r][c], ri, b1s[f]));
                        }
                    }
                }
            }
        }
        __syncthreads();
    }

    // ---- Phase 3: layer-2 projection feats2[h2][n][f2] = h1 @ W2[h2] ----
    for (int idx = tid; idx < NN * 4; idx += NTHREADS) hacc[idx] = 0.f;
    for (int idx = tid; idx < H2_ * NN * F2_; idx += NTHREADS) {
        int h2 = idx / (NN * F2_);
        int rem = idx - h2 * NN * F2_;
        int n = rem / F2_, f2 = rem - n * F2_;
        const float* w = W2s + h2 * HF * F2_ + f2;
        const float* xr = Xh + n * XH_STRIDE;
        float s = 0.f;
        for (int k = 0; k < HF; k++) s = fmaf(xr[k], w[k * F2_], s);
        f2s[(h2 * NN + n) * 4 + f2] = s;
    }
    __syncthreads();
    for (int idx = tid; idx < H2_ * NN; idx += NTHREADS) {
        int h2 = idx / NN, n = idx - h2 * NN;
        const float* fp = f2s + (h2 * NN + n) * 4;
        float ss = 0.f, sn = 0.f;
#pragma unroll
        for (int f = 0; f < F2_; f++) {
            ss = fmaf(fp[f], as2s[h2 * F2_ + f], ss);
            sn = fmaf(fp[f], an2s[h2 * F2_ + f], sn);
        }
        es2[idx] = ss;
        en2[idx] = sn;
    }
    __syncthreads();

    // ---- Phase 4: layer-2 attention + aggregation (sum heads into hacc) ----
    for (int h2 = 0; h2 < H2_; h2++) {
        for (int n = wid; n < NN; n += 8) {
            const float es = es2[h2 * NN + n];
            const float* Arow = Ab + n * NN;
            float vmax = -3.4e38f;
            for (int m = lane; m < NN; m += 32) {
                float v = lrelu(es + en2[h2 * NN + m]);
                if (Arow[m] <= 0.f) v = NEGV;
                uni[n * ATT_STRIDE + m] = v;
                vmax = fmaxf(vmax, v);
            }
            vmax = warp_max(vmax);
            float s = 0.f;
            for (int m = lane; m < NN; m += 32) {
                float ev = __expf(uni[n * ATT_STRIDE + m] - vmax);
                uni[n * ATT_STRIDE + m] = ev;
                s += ev;
            }
            s = warp_sum(s);
            if (lane == 0) rinv[n] = 1.f / s;
        }
        __syncthreads();
        for (int idx = tid; idx < NN * F2_; idx += NTHREADS) {
            int n = idx / F2_, f2 = idx - n * F2_;
            const float* ar = uni + n * ATT_STRIDE;
            const float* fp = f2s + h2 * NN * 4 + f2;
            float s = 0.f;
            for (int m = 0; m < NN; m++) s = fmaf(ar[m], fp[m * 4], s);
            hacc[n * 4 + f2] += s * rinv[n];
        }
        __syncthreads();
    }

    // ---- Phase 5: node probs t[n] = sigmoid( lrelu(mean_h + b2) . fc1 ) ----
    for (int n = tid; n < NN; n += NTHREADS) {
        float z = 0.f;
#pragma unroll
        for (int f2 = 0; f2 < F2_; f2++)
            z = fmaf(lrelu(fmaf(hacc[n * 4 + f2], (1.f / 3.f), b2s[f2])), fc1s[f2], z);
        ts[n] = sigm(z);
    }
    __syncthreads();

    // ---- Phase 6: MIL attention pooling: u = t @ fc2 ; out = sum t*softmax(u) ----
    for (int m = tid; m < NN; m += NTHREADS) {
        float s = 0.f;
        for (int n = 0; n < NN; n++) s = fmaf(ts[n], fc2[n * NN + m], s);
        us[m] = s;
    }
    __syncthreads();
    if (wid == 0) {
        float vmax = -3.4e38f;
        for (int m = lane; m < NN; m += 32) vmax = fmaxf(vmax, us[m]);
        vmax = warp_max(vmax);
        float num = 0.f, den = 0.f;
        for (int m = lane; m < NN; m += 32) {
            float e = __expf(us[m] - vmax);
            num = fmaf(ts[m], e, num);
            den += e;
        }
        num = warp_sum(num);
        den = warp_sum(den);
        if (lane == 0) out[b] = num / den;
    }
}

extern "C" void kernel_launch(void* const* d_in, const int* in_sizes, int n_in,
                              void* d_out, int out_size)
{
    const float* X   = (const float*)d_in[0];
    const float* A   = (const float*)d_in[1];
    const float* M   = (const float*)d_in[2];
    const float* W1  = (const float*)d_in[3];
    const float* as1 = (const float*)d_in[4];
    const float* an1 = (const float*)d_in[5];
    const float* b1  = (const float*)d_in[6];
    const float* W2  = (const float*)d_in[7];
    const float* as2 = (const float*)d_in[8];
    const float* an2 = (const float*)d_in[9];
    const float* b2  = (const float*)d_in[10];
    const float* fc1 = (const float*)d_in[11];
    const float* fc2 = (const float*)d_in[12];
    float* out = (float*)d_out;

    const int B = in_sizes[0] / (NN * NN);

    cudaFuncSetAttribute(gatmil_kernel, cudaFuncAttributeMaxDynamicSharedMemorySize, SMEM_BYTES);
    gatmil_kernel<<<B, NTHREADS, SMEM_BYTES>>>(X, A, M, W1, as1, an1, b1,
                                               W2, as2, an2, b2, fc1, fc2, out);
}

// round 3
// speedup vs baseline: 1.4684x; 1.4684x over previous
#include <cuda_runtime.h>
#include <math.h>

#define NN 110
#define H1_ 5
#define F1_ 24
#define HF 120          // H1*F1
#define H2_ 3
#define F2_ 3
#define XS 121          // stride for Xh (Xm/h1) and attn buffers
#define NEGV -9e15f
#define ALPHA 0.2f
#define NT 512

__device__ __forceinline__ float lrelu(float v) { return v > 0.f ? v : ALPHA * v; }
__device__ __forceinline__ float sigm(float v) { return 1.f / (1.f + __expf(-v)); }

__device__ __forceinline__ float warp_max(float v) {
#pragma unroll
    for (int o = 16; o > 0; o >>= 1) v = fmaxf(v, __shfl_xor_sync(0xffffffffu, v, o));
    return v;
}
__device__ __forceinline__ float warp_sum(float v) {
#pragma unroll
    for (int o = 16; o > 0; o >>= 1) v += __shfl_xor_sync(0xffffffffu, v, o);
    return v;
}

// smem floats:
// Xh 13310 | feats 13200 | attn 13310 (W1 staging first) | es1/en1/rmax1/rinv1 550 ea
// as1s/an1s 120 ea, b1s 24 | W2s 1080, as2s 9, an2s 9, b2s 3, fc1s 3 | f2s 1320
// es2/en2/rmax2/rinv2 330 ea | hacc 440 | ts 110 | us 110 | Amask 440 (uint)
#define SMEM_FLOATS (13310 + 13200 + 13310 + 4*550 + 264 + 1104 + 1320 + 4*330 + 440 + 220 + 440)
#define SMEM_BYTES (SMEM_FLOATS * 4)

__global__ __launch_bounds__(NT, 1)
void gatmil_kernel(const float* __restrict__ X, const float* __restrict__ A,
                   const float* __restrict__ M,
                   const float* __restrict__ W1, const float* __restrict__ as1,
                   const float* __restrict__ an1, const float* __restrict__ b1,
                   const float* __restrict__ W2, const float* __restrict__ as2,
                   const float* __restrict__ an2, const float* __restrict__ b2,
                   const float* __restrict__ fc1, const float* __restrict__ fc2,
                   float* __restrict__ out)
{
    extern __shared__ float sm[];
    float* Xh    = sm;                    // 13310
    float* feats = Xh + NN * XS;          // 13200
    float* attn  = feats + H1_ * NN * F1_;// 13310
    float* es1   = attn + NN * XS;        // 550
    float* en1   = es1 + H1_ * NN;
    float* rmax1 = en1 + H1_ * NN;
    float* rinv1 = rmax1 + H1_ * NN;
    float* as1s  = rinv1 + H1_ * NN;      // 120
    float* an1s  = as1s + HF;             // 120
    float* b1s   = an1s + HF;             // 24
    float* W2s   = b1s + F1_;             // 1080
    float* as2s  = W2s + H2_ * HF * F2_;  // 9
    float* an2s  = as2s + 9;              // 9
    float* b2s   = an2s + 9;              // 3
    float* fc1s  = b2s + 3;               // 3
    float* f2s   = fc1s + 3;              // 1320 [h2][n][4]
    float* es2   = f2s + H2_ * NN * 4;    // 330
    float* en2   = es2 + H2_ * NN;
    float* rmax2 = en2 + H2_ * NN;
    float* rinv2 = rmax2 + H2_ * NN;
    float* hacc  = rinv2 + H2_ * NN;      // 440
    float* ts    = hacc + NN * 4;         // 110
    float* us    = ts + NN;               // 110
    unsigned* Amask = (unsigned*)(us + NN); // 440 words

    const int b = blockIdx.x;
    const int tid = threadIdx.x;
    const int lane = tid & 31;
    const int wid = tid >> 5;

    const float* Xb = X + (size_t)b * NN * NN;
    const float* Ab = A + (size_t)b * NN * NN;

    // ---- Phase 0: stage weights, masked input, adjacency bitmask ----
    for (int i = tid; i < HF; i += NT) { as1s[i] = as1[i]; an1s[i] = an1[i]; }
    if (tid < F1_) b1s[tid] = b1[tid];
    for (int i = tid; i < H2_ * HF * F2_; i += NT) W2s[i] = W2[i];
    if (tid < H2_ * F2_) { as2s[tid] = as2[tid]; an2s[tid] = an2[tid]; }
    if (tid < F2_) { b2s[tid] = b2[tid]; fc1s[tid] = fc1[tid]; }
    // W1 -> attn buffer as [i][120]
    for (int idx = tid; idx < NN * HF; idx += NT) {
        int i = idx / HF, col = idx - i * HF;
        int h = col / F1_, f = col - h * F1_;
        attn[idx] = W1[(h * NN + i) * F1_ + f];
    }
    // Xm = X * sigmoid(M)
    for (int idx = tid; idx < NN * NN; idx += NT) {
        int n = idx / NN, i2 = idx - n * NN;
        Xh[n * XS + i2] = Xb[idx] * sigm(M[idx]);
    }
    // adjacency bitmask via ballot (coalesced reads of A)
    for (int w = wid; w < NN * 4; w += NT / 32) {
        int n = w >> 2, seg = w & 3;
        int m = seg * 32 + lane;
        float a = (m < NN) ? Ab[n * NN + m] : 0.f;
        unsigned bal = __ballot_sync(0xffffffffu, a > 0.f);
        if (lane == 0) Amask[w] = bal;
    }
    __syncthreads();

    // ---- Phase 1: feats = Xm @ W1 (110x110 @ 110x120), tiles 2x15, 440 thr ----
    if (tid < 440) {
        int rowg = tid >> 3, colg = tid & 7;
        int n0 = rowg * 2, c0 = colg * 15;
        float acc0[15], acc1[15];
#pragma unroll
        for (int c = 0; c < 15; c++) { acc0[c] = 0.f; acc1[c] = 0.f; }
        const float* xr0 = Xh + n0 * XS;
        const float* xr1 = xr0 + XS;
#pragma unroll 2
        for (int i = 0; i < NN; i++) {
            float a0 = xr0[i], a1 = xr1[i];
            const float* wrow = attn + i * HF + c0;
#pragma unroll
            for (int c = 0; c < 15; c++) {
                float w = wrow[c];
                acc0[c] = fmaf(a0, w, acc0[c]);
                acc1[c] = fmaf(a1, w, acc1[c]);
            }
        }
#pragma unroll
        for (int c = 0; c < 15; c++) {
            int col = c0 + c; int h = col / F1_, f = col - h * F1_;
            feats[(h * NN + n0) * F1_ + f]     = acc0[c];
            feats[(h * NN + n0 + 1) * F1_ + f] = acc1[c];
        }
    }
    __syncthreads();

    // ---- Phase 1b: attention logit halves ----
    for (int idx = tid; idx < H1_ * NN; idx += NT) {
        int h = idx / NN;
        const float* fp = feats + idx * F1_;
        const float* ap = as1s + h * F1_;
        const float* np = an1s + h * F1_;
        float ss = 0.f, sn = 0.f;
#pragma unroll
        for (int f = 0; f < F1_; f++) { float v = fp[f]; ss = fmaf(v, ap[f], ss); sn = fmaf(v, np[f], sn); }
        es1[idx] = ss; en1[idx] = sn;
    }
    __syncthreads();

    // ---- Phase 1c: softmax stats for ALL heads (recompute logits, no storage) ----
    for (int row = wid; row < H1_ * NN; row += NT / 32) {
        int h = row / NN, n = row - h * NN;
        float es = es1[row];
        const float* enh = en1 + h * NN;
        const unsigned* am = Amask + n * 4;
        float vmax = -3.4e38f;
#pragma unroll
        for (int it = 0; it < 4; it++) {
            int m = it * 32 + lane;
            if (m < NN) {
                float v = es + enh[m];
                v = v > 0.f ? v : ALPHA * v;
                if (!((am[it] >> lane) & 1u)) v = NEGV;
                vmax = fmaxf(vmax, v);
            }
        }
        vmax = warp_max(vmax);
        float s = 0.f;
#pragma unroll
        for (int it = 0; it < 4; it++) {
            int m = it * 32 + lane;
            if (m < NN) {
                float v = es + enh[m];
                v = v > 0.f ? v : ALPHA * v;
                if (!((am[it] >> lane) & 1u)) v = NEGV;
                s += __expf(v - vmax);
            }
        }
        s = warp_sum(s);
        if (lane == 0) { rmax1[row] = vmax; rinv1[row] = 1.f / s; }
    }
    __syncthreads();

    // ---- Phase 2: per-head materialize exp + aggregation GEMM -> h1 in Xh ----
    for (int h = 0; h < H1_; h++) {
        const float* enh = en1 + h * NN;
        const float* esh = es1 + h * NN;
        const float* rmh = rmax1 + h * NN;
        for (int idx = tid; idx < NN * NN; idx += NT) {
            int n = idx / NN, m = idx - n * NN;
            float v = esh[n] + enh[m];
            v = v > 0.f ? v : ALPHA * v;
            if (!((Amask[n * 4 + (m >> 5)] >> (m & 31)) & 1u)) v = NEGV;
            attn[n * XS + m] = __expf(v - rmh[n]);
        }
        __syncthreads();
        if (tid < 440) {
            int rowg = tid >> 3, colg = tid & 7;
            int n0 = rowg * 2, f0 = colg * 3;
            float acc0[3] = {0.f, 0.f, 0.f}, acc1[3] = {0.f, 0.f, 0.f};
            const float* ar0 = attn + n0 * XS;
            const float* ar1 = ar0 + XS;
            const float* fh = feats + h * NN * F1_ + f0;
#pragma unroll 2
            for (int m = 0; m < NN; m++) {
                float a0 = ar0[m], a1 = ar1[m];
                const float* w = fh + m * F1_;
#pragma unroll
                for (int c = 0; c < 3; c++) {
                    acc0[c] = fmaf(a0, w[c], acc0[c]);
                    acc1[c] = fmaf(a1, w[c], acc1[c]);
                }
            }
            float r0 = rinv1[h * NN + n0], r1 = rinv1[h * NN + n0 + 1];
#pragma unroll
            for (int c = 0; c < 3; c++) {
                int f = f0 + c;
                Xh[n0 * XS + h * F1_ + f]       = lrelu(fmaf(acc0[c], r0, b1s[f]));
                Xh[(n0 + 1) * XS + h * F1_ + f] = lrelu(fmaf(acc1[c], r1, b1s[f]));
            }
        }
        __syncthreads();
    }

    // ---- Phase 3: layer-2 projection f2s[h2][n][f2] = h1 @ W2 ----
    for (int idx = tid; idx < NN * 4; idx += NT) hacc[idx] = 0.f;
    for (int idx = tid; idx < H2_ * NN * F2_; idx += NT) {
        int h2 = idx / (NN * F2_);
        int rem = idx - h2 * (NN * F2_);
        int n = rem / F2_, f2 = rem - n * F2_;
        const float* w = W2s + h2 * HF * F2_ + f2;
        const float* xr = Xh + n * XS;
        float s = 0.f;
#pragma unroll 4
        for (int k = 0; k < HF; k++) s = fmaf(xr[k], w[k * F2_], s);
        f2s[(h2 * NN + n) * 4 + f2] = s;
    }
    __syncthreads();
    for (int idx = tid; idx < H2_ * NN; idx += NT) {
        int h2 = idx / NN;
        const float* fp = f2s + idx * 4;
        float ss = 0.f, sn = 0.f;
#pragma unroll
        for (int f = 0; f < F2_; f++) { ss = fmaf(fp[f], as2s[h2 * F2_ + f], ss); sn = fmaf(fp[f], an2s[h2 * F2_ + f], sn); }
        es2[idx] = ss; en2[idx] = sn;
    }
    __syncthreads();
    // layer-2 softmax stats
    for (int row = wid; row < H2_ * NN; row += NT / 32) {
        int h2 = row / NN, n = row - h2 * NN;
        float es = es2[row];
        const float* enh = en2 + h2 * NN;
        const unsigned* am = Amask + n * 4;
        float vmax = -3.4e38f;
#pragma unroll
        for (int it = 0; it < 4; it++) {
            int m = it * 32 + lane;
            if (m < NN) {
                float v = es + enh[m];
                v = v > 0.f ? v : ALPHA * v;
                if (!((am[it] >> lane) & 1u)) v = NEGV;
                vmax = fmaxf(vmax, v);
            }
        }
        vmax = warp_max(vmax);
        float s = 0.f;
#pragma unroll
        for (int it = 0; it < 4; it++) {
            int m = it * 32 + lane;
            if (m < NN) {
                float v = es + enh[m];
                v = v > 0.f ? v : ALPHA * v;
                if (!((am[it] >> lane) & 1u)) v = NEGV;
                s += __expf(v - vmax);
            }
        }
        s = warp_sum(s);
        if (lane == 0) { rmax2[row] = vmax; rinv2[row] = 1.f / s; }
    }
    __syncthreads();

    // ---- Phase 4: layer-2 attention + aggregation (heads summed into hacc) ----
    for (int h2 = 0; h2 < H2_; h2++) {
        const float* esh = es2 + h2 * NN;
        const float* enh = en2 + h2 * NN;
        const float* rmh = rmax2 + h2 * NN;
        for (int idx = tid; idx < NN * NN; idx += NT) {
            int n = idx / NN, m = idx - n * NN;
            float v = esh[n] + enh[m];
            v = v > 0.f ? v : ALPHA * v;
            if (!((Amask[n * 4 + (m >> 5)] >> (m & 31)) & 1u)) v = NEGV;
            attn[n * XS + m] = __expf(v - rmh[n]);
        }
        __syncthreads();
        if (tid < 448) {                       // 14 full warps: shfl-safe
            int n = tid >> 2, q = tid & 3;     // split-K by 4
            float acc[3] = {0.f, 0.f, 0.f};
            if (n < NN) {
                const float* ar = attn + n * XS;
                const float* fh = f2s + (h2 * NN) * 4;
                int m0 = q * 28, m1 = m0 + 28 < NN ? m0 + 28 : NN;
                for (int m = m0; m < m1; m++) {
                    float a = ar[m];
                    const float* w = fh + m * 4;
                    acc[0] = fmaf(a, w[0], acc[0]);
                    acc[1] = fmaf(a, w[1], acc[1]);
                    acc[2] = fmaf(a, w[2], acc[2]);
                }
            }
#pragma unroll
            for (int c = 0; c < 3; c++) {
                acc[c] += __shfl_xor_sync(0xffffffffu, acc[c], 1);
                acc[c] += __shfl_xor_sync(0xffffffffu, acc[c], 2);
            }
            if (q == 0 && n < NN) {
                float r = rinv2[h2 * NN + n];
                hacc[n * 4 + 0] += acc[0] * r;
                hacc[n * 4 + 1] += acc[1] * r;
                hacc[n * 4 + 2] += acc[2] * r;
            }
        }
        __syncthreads();
    }

    // ---- Phase 5: node probs ----
    for (int n = tid; n < NN; n += NT) {
        float z = 0.f;
#pragma unroll
        for (int f = 0; f < F2_; f++)
            z = fmaf(lrelu(fmaf(hacc[n * 4 + f], (1.f / 3.f), b2s[f])), fc1s[f], z);
        ts[n] = sigm(z);
    }
    __syncthreads();

    // ---- Phase 6: MIL pooling ----
    if (tid < 448) {
        int m = tid >> 2, q = tid & 3;
        float s = 0.f;
        if (m < NN) {
            int n0 = q * 28, n1 = n0 + 28 < NN ? n0 + 28 : NN;
            for (int n = n0; n < n1; n++) s = fmaf(ts[n], fc2[n * NN + m], s);
        }
        s += __shfl_xor_sync(0xffffffffu, s, 1);
        s += __shfl_xor_sync(0xffffffffu, s, 2);
        if (q == 0 && m < NN) us[m] = s;
    }
    __syncthreads();
    if (wid == 0) {
        float vmax = -3.4e38f;
        for (int m = lane; m < NN; m += 32) vmax = fmaxf(vmax, us[m]);
        vmax = warp_max(vmax);
        float num = 0.f, den = 0.f;
        for (int m = lane; m < NN; m += 32) {
            float e = __expf(us[m] - vmax);
            num = fmaf(ts[m], e, num);
            den += e;
        }
        num = warp_sum(num);
        den = warp_sum(den);
        if (lane == 0) out[b] = num / den;
    }
}

extern "C" void kernel_launch(void* const* d_in, const int* in_sizes, int n_in,
                              void* d_out, int out_size)
{
    const float* X   = (const float*)d_in[0];
    const float* A   = (const float*)d_in[1];
    const float* M   = (const float*)d_in[2];
    const float* W1  = (const float*)d_in[3];
    const float* as1 = (const float*)d_in[4];
    const float* an1 = (const float*)d_in[5];
    const float* b1  = (const float*)d_in[6];
    const float* W2  = (const float*)d_in[7];
    const float* as2 = (const float*)d_in[8];
    const float* an2 = (const float*)d_in[9];
    const float* b2  = (const float*)d_in[10];
    const float* fc1 = (const float*)d_in[11];
    const float* fc2 = (const float*)d_in[12];
    float* out = (float*)d_out;

    const int B = in_sizes[0] / (NN * NN);

    cudaFuncSetAttribute(gatmil_kernel, cudaFuncAttributeMaxDynamicSharedMemorySize, SMEM_BYTES);
    gatmil_kernel<<<B, NT, SMEM_BYTES>>>(X, A, M, W1, as1, an1, b1,
                                         W2, as2, an2, b2, fc1, fc2, out);
}

// round 4
// speedup vs baseline: 1.4817x; 1.0091x over previous
#include <cuda_runtime.h>
#include <math.h>

#define NN 110
#define XS 122      // Xh row stride (even -> 8B aligned rows, conflict-free P1 gathers)
#define AS 113      // attn row stride (odd -> conflict-free column gathers)
#define FHS 2644    // per-head stride for feats/W1s (16B aligned, banks spread for 5 heads)
#define NT 512
#define ALPHA 0.2f

typedef unsigned long long u64;

__device__ __forceinline__ u64 ffma2(u64 a, u64 b, u64 c) {
    u64 d; asm("fma.rn.f32x2 %0, %1, %2, %3;" : "=l"(d) : "l"(a), "l"(b), "l"(c)); return d;
}
__device__ __forceinline__ u64 splat2(float x) {
    u64 d; asm("mov.b64 %0, {%1, %1};" : "=l"(d) : "f"(x)); return d;
}
__device__ __forceinline__ float2 unpack2(u64 v) {
    float2 r; asm("mov.b64 {%0, %1}, %2;" : "=f"(r.x), "=f"(r.y) : "l"(v)); return r;
}
__device__ __forceinline__ float lrelu(float v) { return v > 0.f ? v : ALPHA * v; }
__device__ __forceinline__ float sigm(float v) { return 1.f / (1.f + __expf(-v)); }
__device__ __forceinline__ float warp_sum(float v) {
#pragma unroll
    for (int o = 16; o > 0; o >>= 1) v += __shfl_xor_sync(0xffffffffu, v, o);
    return v;
}
__device__ __forceinline__ float warp_max(float v) {
#pragma unroll
    for (int o = 16; o > 0; o >>= 1) v = fmaxf(v, __shfl_xor_sync(0xffffffffu, v, o));
    return v;
}

// smem float offsets (all 16B aligned where vector-loaded)
#define OFF_XH    0                       // 13420 = 110*122
#define OFF_FEATS (OFF_XH + 13420)        // 13220 = 5*2644
#define OFF_ATTN  (OFF_FEATS + 13220)     // 13312 (W1s staging, then attn 110*113)
#define OFF_ES1   (OFF_ATTN + 13312)      // 552
#define OFF_EN1   (OFF_ES1 + 552)         // 552
#define OFF_RI1   (OFF_EN1 + 552)         // 552
#define OFF_AS1   (OFF_RI1 + 552)         // 120
#define OFF_AN1   (OFF_AS1 + 120)         // 120
#define OFF_B1    (OFF_AN1 + 120)         // 24
#define OFF_W2C   (OFF_B1 + 24)           // 1464 = 12*122
#define OFF_AS2   (OFF_W2C + 1464)        // 12
#define OFF_AN2   (OFF_AS2 + 12)          // 12
#define OFF_B2    (OFF_AN2 + 12)          // 4
#define OFF_FC1   (OFF_B2 + 4)            // 4
#define OFF_F2S   (OFF_FC1 + 4)           // 1320 = 3*110*4
#define OFF_ES2   (OFF_F2S + 1320)        // 332
#define OFF_EN2   (OFF_ES2 + 332)         // 332
#define OFF_RI2   (OFF_EN2 + 332)         // 332
#define OFF_TS    (OFF_RI2 + 332)         // 112
#define OFF_US    (OFF_TS + 112)          // 112
#define OFF_AM    (OFF_US + 112)          // 440 uints
#define SMEM_FLOATS (OFF_AM + 440)
#define SMEM_BYTES (SMEM_FLOATS * 4)

__global__ __launch_bounds__(NT, 1)
void gatmil_kernel(const float* __restrict__ X, const float* __restrict__ A,
                   const float* __restrict__ M,
                   const float* __restrict__ W1, const float* __restrict__ as1,
                   const float* __restrict__ an1, const float* __restrict__ b1,
                   const float* __restrict__ W2, const float* __restrict__ as2,
                   const float* __restrict__ an2, const float* __restrict__ b2,
                   const float* __restrict__ fc1, const float* __restrict__ fc2,
                   float* __restrict__ out)
{
    extern __shared__ float sm[];
    float* Xh    = sm + OFF_XH;
    float* feats = sm + OFF_FEATS;
    float* attn  = sm + OFF_ATTN;   // W1s first, then attention exp buffer
    float* es1   = sm + OFF_ES1;
    float* en1   = sm + OFF_EN1;
    float* ri1   = sm + OFF_RI1;
    float* as1s  = sm + OFF_AS1;
    float* an1s  = sm + OFF_AN1;
    float* b1s   = sm + OFF_B1;
    float* W2c   = sm + OFF_W2C;    // [c=h2*4+f2][k] rows of 122, f2==3 rows zero
    float* as2s  = sm + OFF_AS2;
    float* an2s  = sm + OFF_AN2;
    float* b2s   = sm + OFF_B2;
    float* fc1s  = sm + OFF_FC1;
    float* f2s   = sm + OFF_F2S;    // [h2][n][4] (pad col zero)
    float* es2   = sm + OFF_ES2;
    float* en2   = sm + OFF_EN2;
    float* ri2   = sm + OFF_RI2;
    float* ts    = sm + OFF_TS;
    float* us    = sm + OFF_US;
    unsigned* Amask = (unsigned*)(sm + OFF_AM);

    const int b = blockIdx.x;
    const int tid = threadIdx.x;
    const int lane = tid & 31;
    const int wid = tid >> 5;

    const float* Xb = X + (size_t)b * NN * NN;
    const float* Ab = A + (size_t)b * NN * NN;

    // ================= P0: stage everything =================
    // W1 verbatim per head (padded stride)
    for (int h = 0; h < 5; h++)
        for (int j = tid; j < 2640; j += NT)
            attn[h * FHS + j] = W1[h * 2640 + j];
    for (int i = tid; i < 120; i += NT) { as1s[i] = as1[i]; an1s[i] = an1[i]; }
    if (tid < 24) b1s[tid] = b1[tid];
    // W2 -> [c][k], c = h2*4+f2, f2==3 rows zero
    for (int idx = tid; idx < 12 * 122; idx += NT) {
        int c = idx / 122, k = idx - c * 122;
        float v = 0.f;
        int f2 = c & 3, h2 = c >> 2;
        if (k < 120 && f2 < 3) v = W2[(h2 * 120 + k) * 3 + f2];
        W2c[idx] = v;
    }
    if (tid < 9) { as2s[(tid / 3) * 3 + tid % 3] = as2[tid]; an2s[(tid / 3) * 3 + tid % 3] = an2[tid]; }
    if (tid < 3) { b2s[tid] = b2[tid]; fc1s[tid] = fc1[tid]; }
    // Xm = X * sigmoid(M), warp-per-row coalesced
    for (int n = wid; n < NN; n += 16)
        for (int i = lane; i < NN; i += 32)
            Xh[n * XS + i] = Xb[n * NN + i] * sigm(M[n * NN + i]);
    // adjacency bitmask
    for (int w = wid; w < NN * 4; w += 16) {
        int n = w >> 2, seg = w & 3;
        int m = seg * 32 + lane;
        float a = (m < NN) ? Ab[n * NN + m] : 0.f;
        unsigned bal = __ballot_sync(0xffffffffu, a > 0.f);
        if (lane == 0) Amask[w] = bal;
    }
    __syncthreads();

    // ================= P1: feats = Xm @ W1  (f32x2, tiles 2 rows x 24 cols) =================
    if (tid < 275) {
        const int h = tid % 5, rowg = tid / 5;
        const int n0 = rowg * 2;
        const float* xr0 = Xh + n0 * XS;
        const float* xr1 = xr0 + XS;
        const float* wb = attn + h * FHS;
        u64 acc0[12], acc1[12];
#pragma unroll
        for (int j = 0; j < 12; j++) { acc0[j] = 0ull; acc1[j] = 0ull; }
#pragma unroll 2
        for (int i = 0; i < NN; i++) {
            u64 s0 = splat2(xr0[i]);
            u64 s1 = splat2(xr1[i]);
            const ulonglong2* w2 = (const ulonglong2*)(wb + i * 24);
#pragma unroll
            for (int jj = 0; jj < 6; jj++) {
                ulonglong2 wv = w2[jj];
                acc0[2*jj]   = ffma2(s0, wv.x, acc0[2*jj]);
                acc1[2*jj]   = ffma2(s1, wv.x, acc1[2*jj]);
                acc0[2*jj+1] = ffma2(s0, wv.y, acc0[2*jj+1]);
                acc1[2*jj+1] = ffma2(s1, wv.y, acc1[2*jj+1]);
            }
        }
        u64* d0 = (u64*)(feats + h * FHS + n0 * 24);
        u64* d1 = (u64*)(feats + h * FHS + (n0 + 1) * 24);
#pragma unroll
        for (int j = 0; j < 12; j++) { d0[j] = acc0[j]; d1[j] = acc1[j]; }
    }
    __syncthreads();

    // ================= P1b: logit halves es1/en1 (f32x2 dots) =================
    for (int row = tid; row < 550; row += NT) {
        int h = row / NN, n = row - h * NN;
        const ulonglong2* fp = (const ulonglong2*)(feats + h * FHS + n * 24);
        const ulonglong2* ap = (const ulonglong2*)(as1s + h * 24);
        const ulonglong2* np = (const ulonglong2*)(an1s + h * 24);
        u64 sa = 0ull, sb = 0ull;
#pragma unroll
        for (int jj = 0; jj < 6; jj++) {
            ulonglong2 f = fp[jj], av = ap[jj], nv = np[jj];
            sa = ffma2(f.x, av.x, sa); sa = ffma2(f.y, av.y, sa);
            sb = ffma2(f.x, nv.x, sb); sb = ffma2(f.y, nv.y, sb);
        }
        float2 xa = unpack2(sa), xb = unpack2(sb);
        es1[row] = xa.x + xa.y;
        en1[row] = xb.x + xb.y;
    }
    __syncthreads();

    // ================= P2: per-head softmax (no max pass) + aggregation =================
    const int an3 = tid / 3;            // agg mapping: 330 threads, 1 row x 8 cols
    const int af0 = (tid - an3 * 3) * 8;
    for (int h = 0; h < 5; h++) {
        // materialize exp + row sums, warp per row
        for (int n = wid; n < NN; n += 16) {
            const float es = es1[h * NN + n];
            const float* enh = en1 + h * NN;
            float sum = 0.f;
#pragma unroll
            for (int k = 0; k < 4; k++) {
                int m = k * 32 + lane;
                if (m < NN) {
                    float v = 0.f;
                    unsigned am = Amask[n * 4 + k];
                    if ((am >> lane) & 1u) v = __expf(lrelu(es + enh[m]));
                    attn[n * AS + m] = v;
                    sum += v;
                }
            }
            sum = warp_sum(sum);
            if (lane == 0) ri1[h * NN + n] = 1.f / sum;
        }
        __syncthreads();
        // aggregation: h1[n][h*24+f] = lrelu(rinv * (attn @ feats_h) + b1)
        if (tid < 330) {
            const float* ar = attn + an3 * AS;
            const float* fb = feats + h * FHS + af0;
            u64 a0 = 0ull, a1 = 0ull, a2 = 0ull, a3 = 0ull;
#pragma unroll 2
            for (int m = 0; m < NN; m++) {
                u64 s = splat2(ar[m]);
                const ulonglong2* w = (const ulonglong2*)(fb + m * 24);
                ulonglong2 w0 = w[0], w1 = w[1];
                a0 = ffma2(s, w0.x, a0); a1 = ffma2(s, w0.y, a1);
                a2 = ffma2(s, w1.x, a2); a3 = ffma2(s, w1.y, a3);
            }
            float r = ri1[h * NN + an3];
            float* dst = Xh + an3 * XS + h * 24 + af0;
            const float* bb = b1s + af0;
            float2 v0 = unpack2(a0), v1 = unpack2(a1), v2 = unpack2(a2), v3 = unpack2(a3);
            dst[0] = lrelu(fmaf(v0.x, r, bb[0])); dst[1] = lrelu(fmaf(v0.y, r, bb[1]));
            dst[2] = lrelu(fmaf(v1.x, r, bb[2])); dst[3] = lrelu(fmaf(v1.y, r, bb[3]));
            dst[4] = lrelu(fmaf(v2.x, r, bb[4])); dst[5] = lrelu(fmaf(v2.y, r, bb[5]));
            dst[6] = lrelu(fmaf(v3.x, r, bb[6])); dst[7] = lrelu(fmaf(v3.y, r, bb[7]));
        }
        __syncthreads();
    }

    // ================= P3: layer-2 projection f2s = h1 @ W2 (f32x2 dots) =================
    for (int idx = tid; idx < NN * 12; idx += NT) {
        int n = idx / 12, c = idx - n * 12;
        const u64* xr = (const u64*)(Xh + n * XS);
        const u64* wr = (const u64*)(W2c + c * 122);
        u64 acc0 = 0ull, acc1 = 0ull;
#pragma unroll 6
        for (int k2 = 0; k2 < 60; k2 += 2) {
            acc0 = ffma2(xr[k2], wr[k2], acc0);
            acc1 = ffma2(xr[k2 + 1], wr[k2 + 1], acc1);
        }
        float2 v0 = unpack2(acc0), v1 = unpack2(acc1);
        f2s[(c >> 2) * (NN * 4) + n * 4 + (c & 3)] = (v0.x + v0.y) + (v1.x + v1.y);
    }
    __syncthreads();
    for (int idx = tid; idx < 330; idx += NT) {
        int h2 = idx / NN;
        int n = idx - h2 * NN;
        const float* fp = f2s + h2 * (NN * 4) + n * 4;
        float ss = 0.f, sn = 0.f;
#pragma unroll
        for (int f = 0; f < 3; f++) {
            ss = fmaf(fp[f], as2s[h2 * 3 + f], ss);
            sn = fmaf(fp[f], an2s[h2 * 3 + f], sn);
        }
        es2[idx] = ss; en2[idx] = sn;
    }
    __syncthreads();

    // ================= P4: layer-2 attention + aggregation (head partials in regs) =================
    const int qn = tid >> 2, qq = tid & 3;   // split-K x4 over 448 threads
    float tot0 = 0.f, tot1 = 0.f, tot2 = 0.f;
    for (int h2 = 0; h2 < 3; h2++) {
        for (int n = wid; n < NN; n += 16) {
            const float es = es2[h2 * NN + n];
            const float* enh = en2 + h2 * NN;
            float sum = 0.f;
#pragma unroll
            for (int k = 0; k < 4; k++) {
                int m = k * 32 + lane;
                if (m < NN) {
                    float v = 0.f;
                    unsigned am = Amask[n * 4 + k];
                    if ((am >> lane) & 1u) v = __expf(lrelu(es + enh[m]));
                    attn[n * AS + m] = v;
                    sum += v;
                }
            }
            sum = warp_sum(sum);
            if (lane == 0) ri2[h2 * NN + n] = 1.f / sum;
        }
        __syncthreads();
        if (tid < 448) {
            u64 p0 = 0ull, p1 = 0ull;
            if (qn < NN) {
                const float* ar = attn + qn * AS;
                const ulonglong2* wb = (const ulonglong2*)(f2s + h2 * (NN * 4));
                int m0 = qq * 28, m1 = m0 + 28 < NN ? m0 + 28 : NN;
                for (int m = m0; m < m1; m++) {
                    u64 s = splat2(ar[m]);
                    ulonglong2 w = wb[m];
                    p0 = ffma2(s, w.x, p0);
                    p1 = ffma2(s, w.y, p1);
                }
            }
            float2 v0 = unpack2(p0), v1 = unpack2(p1);
            float t0 = v0.x, t1 = v0.y, t2 = v1.x;
            t0 += __shfl_xor_sync(0xffffffffu, t0, 1); t0 += __shfl_xor_sync(0xffffffffu, t0, 2);
            t1 += __shfl_xor_sync(0xffffffffu, t1, 1); t1 += __shfl_xor_sync(0xffffffffu, t1, 2);
            t2 += __shfl_xor_sync(0xffffffffu, t2, 1); t2 += __shfl_xor_sync(0xffffffffu, t2, 2);
            if (qq == 0 && qn < NN) {
                float r = ri2[h2 * NN + qn];
                tot0 = fmaf(t0, r, tot0);
                tot1 = fmaf(t1, r, tot1);
                tot2 = fmaf(t2, r, tot2);
            }
        }
        __syncthreads();
    }

    // ================= P5: node probs =================
    if (tid < 448 && qq == 0 && qn < NN) {
        float z = lrelu(fmaf(tot0, (1.f / 3.f), b2s[0])) * fc1s[0]
                + lrelu(fmaf(tot1, (1.f / 3.f), b2s[1])) * fc1s[1]
                + lrelu(fmaf(tot2, (1.f / 3.f), b2s[2])) * fc1s[2];
        ts[qn] = sigm(z);
    }
    __syncthreads();

    // ================= P6: MIL pooling =================
    if (tid < 448) {
        int m = tid >> 2, q = tid & 3;
        float s = 0.f;
        if (m < NN) {
            int n0 = q * 28, n1 = n0 + 28 < NN ? n0 + 28 : NN;
            for (int n = n0; n < n1; n++) s = fmaf(ts[n], fc2[n * NN + m], s);
        }
        s += __shfl_xor_sync(0xffffffffu, s, 1);
        s += __shfl_xor_sync(0xffffffffu, s, 2);
        if ((tid & 3) == 0 && m < NN) us[m] = s;
    }
    __syncthreads();
    if (wid == 0) {
        float vmax = -3.4e38f;
        for (int m = lane; m < NN; m += 32) vmax = fmaxf(vmax, us[m]);
        vmax = warp_max(vmax);
        float num = 0.f, den = 0.f;
        for (int m = lane; m < NN; m += 32) {
            float e = __expf(us[m] - vmax);
            num = fmaf(ts[m], e, num);
            den += e;
        }
        num = warp_sum(num);
        den = warp_sum(den);
        if (lane == 0) out[b] = num / den;
    }
}

extern "C" void kernel_launch(void* const* d_in, const int* in_sizes, int n_in,
                              void* d_out, int out_size)
{
    const float* X   = (const float*)d_in[0];
    const float* A   = (const float*)d_in[1];
    const float* M   = (const float*)d_in[2];
    const float* W1  = (const float*)d_in[3];
    const float* as1 = (const float*)d_in[4];
    const float* an1 = (const float*)d_in[5];
    const float* b1  = (const float*)d_in[6];
    const float* W2  = (const float*)d_in[7];
    const float* as2 = (const float*)d_in[8];
    const float* an2 = (const float*)d_in[9];
    const float* b2  = (const float*)d_in[10];
    const float* fc1 = (const float*)d_in[11];
    const float* fc2 = (const float*)d_in[12];
    float* out = (float*)d_out;

    const int B = in_sizes[0] / (NN * NN);

    cudaFuncSetAttribute(gatmil_kernel, cudaFuncAttributeMaxDynamicSharedMemorySize, SMEM_BYTES);
    gatmil_kernel<<<B, NT, SMEM_BYTES>>>(X, A, M, W1, as1, an1, b1,
                                         W2, as2, an2, b2, fc1, fc2, out);
}

// round 7
// speedup vs baseline: 2.5775x; 1.7395x over previous
#include <cuda_runtime.h>
#include <math.h>

#define NN 110
#define XS 122      // Xh row stride (Xm, then h1)
#define FHS 2644    // per-head stride for feats/W1s (float-offset %4==0 -> 16B aligned)
#define NT 576
#define ALPHA 0.2f

typedef unsigned long long u64;

__device__ __forceinline__ u64 ffma2(u64 a, u64 b, u64 c) {
    u64 d; asm("fma.rn.f32x2 %0, %1, %2, %3;" : "=l"(d) : "l"(a), "l"(b), "l"(c)); return d;
}
__device__ __forceinline__ u64 splat2(float x) {
    u64 d; asm("mov.b64 %0, {%1, %1};" : "=l"(d) : "f"(x)); return d;
}
__device__ __forceinline__ float2 unpack2(u64 v) {
    float2 r; asm("mov.b64 {%0, %1}, %2;" : "=f"(r.x), "=f"(r.y) : "l"(v)); return r;
}
__device__ __forceinline__ float lrelu(float v) { return v > 0.f ? v : ALPHA * v; }
__device__ __forceinline__ float sigm(float v) { return 1.f / (1.f + __expf(-v)); }
__device__ __forceinline__ float warp_sum(float v) {
#pragma unroll
    for (int o = 16; o > 0; o >>= 1) v += __shfl_xor_sync(0xffffffffu, v, o);
    return v;
}
__device__ __forceinline__ float warp_max(float v) {
#pragma unroll
    for (int o = 16; o > 0; o >>= 1) v = fmaxf(v, __shfl_xor_sync(0xffffffffu, v, o));
    return v;
}

// ---- smem layout: NO overlapping regions. All vector bases: float-offset %4==0 ----
#define OFF_XH    0         // 13420 (Xm rows, later h1 rows; stride XS)
#define OFF_FEATS 13420     // 13220 = 5*FHS
#define OFF_W1S   26640     // 13220 = 5*FHS
#define OFF_W2C   39860     // 1488 = 12*124
#define OFF_F2S   41348     // 1320 = 3*110*4
#define OFF_HP    42668     // 1320
#define OFF_ES1   43988     // 550
#define OFF_EN1   44538     // 550
#define OFF_ES2   45088     // 330
#define OFF_EN2   45418     // 330
#define OFF_AS1   45748     // 120
#define OFF_AN1   45868     // 120
#define OFF_B1    45988     // 24
#define OFF_AS2   46012     // 12
#define OFF_AN2   46024     // 12
#define OFF_B2    46036     // 4
#define OFF_FC1   46040     // 4
#define OFF_TS    46044     // 112
#define OFF_US    46156     // 112
#define OFF_AM    46268     // 440 uints
#define SMEM_FLOATS (OFF_AM + 440)
#define SMEM_BYTES (SMEM_FLOATS * 4)

__global__ __launch_bounds__(NT, 1)
void gatmil_kernel(const float* __restrict__ X, const float* __restrict__ A,
                   const float* __restrict__ M,
                   const float* __restrict__ W1, const float* __restrict__ as1,
                   const float* __restrict__ an1, const float* __restrict__ b1,
                   const float* __restrict__ W2, const float* __restrict__ as2,
                   const float* __restrict__ an2, const float* __restrict__ b2,
                   const float* __restrict__ fc1, const float* __restrict__ fc2,
                   float* __restrict__ out)
{
    extern __shared__ float sm[];
    float* Xh    = sm + OFF_XH;
    float* feats = sm + OFF_FEATS;
    float* W1s   = sm + OFF_W1S;
    float* W2c   = sm + OFF_W2C;
    float* f2s   = sm + OFF_F2S;
    float* hp    = sm + OFF_HP;
    float* es1   = sm + OFF_ES1;
    float* en1   = sm + OFF_EN1;
    float* es2   = sm + OFF_ES2;
    float* en2   = sm + OFF_EN2;
    float* as1s  = sm + OFF_AS1;
    float* an1s  = sm + OFF_AN1;
    float* b1s   = sm + OFF_B1;
    float* as2s  = sm + OFF_AS2;
    float* an2s  = sm + OFF_AN2;
    float* b2s   = sm + OFF_B2;
    float* fc1s  = sm + OFF_FC1;
    float* ts    = sm + OFF_TS;
    float* us    = sm + OFF_US;
    unsigned* Amask = (unsigned*)(sm + OFF_AM);

    const int b = blockIdx.x;
    const int tid = threadIdx.x;
    const int lane = tid & 31;
    const int wid = tid >> 5;

    const float* Xb = X + (size_t)b * NN * NN;
    const float* Ab = A + (size_t)b * NN * NN;

    // ================= P0: stage =================
    for (int h = 0; h < 5; h++)
        for (int j = tid; j < 2640; j += NT)
            W1s[h * FHS + j] = W1[h * 2640 + j];
    for (int i = tid; i < 120; i += NT) { as1s[i] = as1[i]; an1s[i] = an1[i]; }
    if (tid < 24) b1s[tid] = b1[tid];
    for (int idx = tid; idx < 12 * 124; idx += NT) {
        int c = idx / 124, k = idx - c * 124;
        int h2 = c >> 2, f2 = c & 3;
        float v = 0.f;
        if (k < 120 && f2 < 3) v = W2[(h2 * 120 + k) * 3 + f2];
        W2c[idx] = v;
    }
    if (tid < 9) { as2s[tid] = as2[tid]; an2s[tid] = an2[tid]; }
    if (tid < 3) { b2s[tid] = b2[tid]; fc1s[tid] = fc1[tid]; }
    for (int n = wid; n < NN; n += NT / 32)
        for (int i = lane; i < NN; i += 32)
            Xh[n * XS + i] = Xb[n * NN + i] * sigm(M[n * NN + i]);
    for (int w = wid; w < NN * 4; w += NT / 32) {
        int n = w >> 2, seg = w & 3;
        int m = seg * 32 + lane;
        float a = (m < NN) ? Ab[n * NN + m] : 0.f;
        unsigned bal = __ballot_sync(0xffffffffu, a > 0.f);
        if (lane == 0) Amask[w] = bal;
    }
    __syncthreads();

    // ================= P1: feats = Xm @ W1 (275 thr, 2x24 tiles) =================
    if (tid < 275) {
        const int h = tid % 5, rowg = tid / 5;
        const int n0 = rowg * 2;
        const float* xr0 = Xh + n0 * XS;
        const float* xr1 = xr0 + XS;
        const float* wb = W1s + h * FHS;
        u64 acc0[12], acc1[12];
#pragma unroll
        for (int j = 0; j < 12; j++) { acc0[j] = 0ull; acc1[j] = 0ull; }
#pragma unroll 2
        for (int i = 0; i < NN; i++) {
            u64 s0 = splat2(xr0[i]);
            u64 s1 = splat2(xr1[i]);
            const ulonglong2* w2 = (const ulonglong2*)(wb + i * 24);
#pragma unroll
            for (int jj = 0; jj < 6; jj++) {
                ulonglong2 wv = w2[jj];
                acc0[2*jj]   = ffma2(s0, wv.x, acc0[2*jj]);
                acc1[2*jj]   = ffma2(s1, wv.x, acc1[2*jj]);
                acc0[2*jj+1] = ffma2(s0, wv.y, acc0[2*jj+1]);
                acc1[2*jj+1] = ffma2(s1, wv.y, acc1[2*jj+1]);
            }
        }
        u64* d0 = (u64*)(feats + h * FHS + n0 * 24);
        u64* d1 = (u64*)(feats + h * FHS + (n0 + 1) * 24);
#pragma unroll
        for (int j = 0; j < 12; j++) { d0[j] = acc0[j]; d1[j] = acc1[j]; }
    }
    __syncthreads();

    // ================= P1b: logit halves =================
    for (int row = tid; row < 550; row += NT) {
        int h = row / NN, n = row - h * NN;
        const ulonglong2* fp = (const ulonglong2*)(feats + h * FHS + n * 24);
        const ulonglong2* ap = (const ulonglong2*)(as1s + h * 24);
        const ulonglong2* np = (const ulonglong2*)(an1s + h * 24);
        u64 sa = 0ull, sb = 0ull;
#pragma unroll
        for (int jj = 0; jj < 6; jj++) {
            ulonglong2 f = fp[jj], av = ap[jj], nv = np[jj];
            sa = ffma2(f.x, av.x, sa); sa = ffma2(f.y, av.y, sa);
            sb = ffma2(f.x, nv.x, sb); sb = ffma2(f.y, nv.y, sb);
        }
        float2 xa = unpack2(sa), xb = unpack2(sb);
        es1[row] = xa.x + xa.y;
        en1[row] = xb.x + xb.y;
    }
    __syncthreads();

    // ========== P2: fused softmax + aggregation, all heads concurrent ==========
    if (tid < 550) {
        const int h = tid / NN, n = tid - h * NN;
        const float es = es1[tid];
        const float* enh = en1 + h * NN;
        const float* fbase = feats + h * FHS;
        unsigned mwr[4];
#pragma unroll
        for (int k = 0; k < 4; k++) mwr[k] = Amask[n * 4 + k];
        u64 acc[12];
#pragma unroll
        for (int j = 0; j < 12; j++) acc[j] = 0ull;
        float sum = 0.f;
#pragma unroll
        for (int k = 0; k < 4; k++) {
            const unsigned mw = mwr[k];
            const int mmax = (k < 3) ? 32 : 14;
#pragma unroll 2
            for (int m2 = 0; m2 < mmax; m2++) {
                int m = k * 32 + m2;
                float v = es + enh[m];
                v = v > 0.f ? v : ALPHA * v;
                float e = __expf(v);
                e = ((mw >> m2) & 1u) ? e : 0.f;
                sum += e;
                u64 s = splat2(e);
                const ulonglong2* w = (const ulonglong2*)(fbase + m * 24);
                ulonglong2 w0 = w[0], w1 = w[1], w2 = w[2], w3 = w[3], w4 = w[4], w5 = w[5];
                acc[0]  = ffma2(s, w0.x, acc[0]);  acc[1]  = ffma2(s, w0.y, acc[1]);
                acc[2]  = ffma2(s, w1.x, acc[2]);  acc[3]  = ffma2(s, w1.y, acc[3]);
                acc[4]  = ffma2(s, w2.x, acc[4]);  acc[5]  = ffma2(s, w2.y, acc[5]);
                acc[6]  = ffma2(s, w3.x, acc[6]);  acc[7]  = ffma2(s, w3.y, acc[7]);
                acc[8]  = ffma2(s, w4.x, acc[8]);  acc[9]  = ffma2(s, w4.y, acc[9]);
                acc[10] = ffma2(s, w5.x, acc[10]); acc[11] = ffma2(s, w5.y, acc[11]);
            }
        }
        const float rinv = 1.f / sum;
        float* dst = Xh + n * XS + h * 24;   // overwrite Xm row n with h1 row n
        // b1 is shape [F1]=[24], SHARED across heads (bias indexed by f only!)
#pragma unroll
        for (int j = 0; j < 12; j++) {
            float2 p = unpack2(acc[j]);
            p.x = lrelu(fmaf(p.x, rinv, b1s[2 * j]));
            p.y = lrelu(fmaf(p.y, rinv, b1s[2 * j + 1]));
            *(float2*)(dst + 2 * j) = p;
        }
    }
    __syncthreads();

    // ================= P3: f2s = h1 @ W2 =================
    for (int idx = tid; idx < NN * 12; idx += NT) {
        int n = idx / 12, c = idx - n * 12;
        const u64* xr = (const u64*)(Xh + n * XS);
        const ulonglong2* wr = (const ulonglong2*)(W2c + c * 124);
        u64 acc0 = 0ull, acc1 = 0ull;
#pragma unroll 5
        for (int j = 0; j < 60; j += 2) {
            ulonglong2 wv = wr[j >> 1];
            acc0 = ffma2(xr[j], wv.x, acc0);
            acc1 = ffma2(xr[j + 1], wv.y, acc1);
        }
        float2 v0 = unpack2(acc0), v1 = unpack2(acc1);
        f2s[(c >> 2) * (NN * 4) + n * 4 + (c & 3)] = (v0.x + v0.y) + (v1.x + v1.y);
    }
    __syncthreads();

    // ================= P3b: layer-2 logit halves =================
    if (tid < 330) {
        int h2 = tid / NN;
        float4 fv = *(const float4*)(f2s + tid * 4);
        es2[tid] = fv.x * as2s[h2 * 3] + fv.y * as2s[h2 * 3 + 1] + fv.z * as2s[h2 * 3 + 2];
        en2[tid] = fv.x * an2s[h2 * 3] + fv.y * an2s[h2 * 3 + 1] + fv.z * an2s[h2 * 3 + 2];
    }
    __syncthreads();

    // ========== P4: fused layer-2 softmax + aggregation ==========
    if (tid < 330) {
        const int h2 = tid / NN, n = tid - h2 * NN;
        const float es = es2[tid];
        const float* enh = en2 + h2 * NN;
        const ulonglong2* fbw = (const ulonglong2*)(f2s + h2 * (NN * 4));
        unsigned mwr[4];
#pragma unroll
        for (int k = 0; k < 4; k++) mwr[k] = Amask[n * 4 + k];
        u64 a0 = 0ull, a1 = 0ull;
        float sum = 0.f;
#pragma unroll
        for (int k = 0; k < 4; k++) {
            const unsigned mw = mwr[k];
            const int mmax = (k < 3) ? 32 : 14;
#pragma unroll 4
            for (int m2 = 0; m2 < mmax; m2++) {
                int m = k * 32 + m2;
                float v = es + enh[m];
                v = v > 0.f ? v : ALPHA * v;
                float e = __expf(v);
                e = ((mw >> m2) & 1u) ? e : 0.f;
                sum += e;
                u64 s = splat2(e);
                ulonglong2 w = fbw[m];
                a0 = ffma2(s, w.x, a0);
                a1 = ffma2(s, w.y, a1);
            }
        }
        const float rinv = 1.f / sum;
        float2 v0 = unpack2(a0), v1 = unpack2(a1);
        float4 o; o.x = v0.x * rinv; o.y = v0.y * rinv; o.z = v1.x * rinv; o.w = 0.f;
        *(float4*)(hp + tid * 4) = o;
    }
    __syncthreads();

    // ================= P5: node probs =================
    if (tid < NN) {
        float4 p0 = *(const float4*)(hp + tid * 4);
        float4 p1 = *(const float4*)(hp + (NN + tid) * 4);
        float4 p2 = *(const float4*)(hp + (2 * NN + tid) * 4);
        float z = lrelu(fmaf((p0.x + p1.x + p2.x), (1.f / 3.f), b2s[0])) * fc1s[0]
                + lrelu(fmaf((p0.y + p1.y + p2.y), (1.f / 3.f), b2s[1])) * fc1s[1]
                + lrelu(fmaf((p0.z + p1.z + p2.z), (1.f / 3.f), b2s[2])) * fc1s[2];
        ts[tid] = sigm(z);
    }
    __syncthreads();

    // ================= P6: MIL pooling =================
    if (tid < 448) {
        int m = tid >> 2, q = tid & 3;
        float s = 0.f;
        if (m < NN) {
            int n0 = q * 28, n1 = n0 + 28 < NN ? n0 + 28 : NN;
            for (int n = n0; n < n1; n++) s = fmaf(ts[n], fc2[n * NN + m], s);
        }
        s += __shfl_xor_sync(0xffffffffu, s, 1);
        s += __shfl_xor_sync(0xffffffffu, s, 2);
        if (q == 0 && m < NN) us[m] = s;
    }
    __syncthreads();
    if (wid == 0) {
        float vmax = -3.4e38f;
        for (int m = lane; m < NN; m += 32) vmax = fmaxf(vmax, us[m]);
        vmax = warp_max(vmax);
        float num = 0.f, den = 0.f;
        for (int m = lane; m < NN; m += 32) {
            float e = __expf(us[m] - vmax);
            num = fmaf(ts[m], e, num);
            den += e;
        }
        num = warp_sum(num);
        den = warp_sum(den);
        if (lane == 0) out[b] = num / den;
    }
}

extern "C" void kernel_launch(void* const* d_in, const int* in_sizes, int n_in,
                              void* d_out, int out_size)
{
    const float* X   = (const float*)d_in[0];
    const float* A   = (const float*)d_in[1];
    const float* M   = (const float*)d_in[2];
    const float* W1  = (const float*)d_in[3];
    const float* as1 = (const float*)d_in[4];
    const float* an1 = (const float*)d_in[5];
    const float* b1  = (const float*)d_in[6];
    const float* W2  = (const float*)d_in[7];
    const float* as2 = (const float*)d_in[8];
    const float* an2 = (const float*)d_in[9];
    const float* b2  = (const float*)d_in[10];
    const float* fc1 = (const float*)d_in[11];
    const float* fc2 = (const float*)d_in[12];
    float* out = (float*)d_out;

    const int B = in_sizes[0] / (NN * NN);

    cudaFuncSetAttribute(gatmil_kernel, cudaFuncAttributeMaxDynamicSharedMemorySize, SMEM_BYTES);
    gatmil_kernel<<<B, NT, SMEM_BYTES>>>(X, A, M, W1, as1, an1, b1,
                                         W2, as2, an2, b2, fc1, fc2, out);
}

// round 8
// speedup vs baseline: 2.6171x; 1.0154x over previous
#include <cuda_runtime.h>
#include <math.h>

#define NN 110
#define XS 122      // Xh row stride (XmT rows, then h1 rows)
#define FHS 2644    // per-head stride for feats/W1s (float-offset %4==0 -> 16B aligned)
#define ENS 112     // padded per-head stride for en1/en2 (float4-loadable)
#define NT 576
#define ALPHA 0.2f

typedef unsigned long long u64;

__device__ __forceinline__ u64 ffma2(u64 a, u64 b, u64 c) {
    u64 d; asm("fma.rn.f32x2 %0, %1, %2, %3;" : "=l"(d) : "l"(a), "l"(b), "l"(c)); return d;
}
__device__ __forceinline__ u64 splat2(float x) {
    u64 d; asm("mov.b64 %0, {%1, %1};" : "=l"(d) : "f"(x)); return d;
}
__device__ __forceinline__ float2 unpack2(u64 v) {
    float2 r; asm("mov.b64 {%0, %1}, %2;" : "=f"(r.x), "=f"(r.y) : "l"(v)); return r;
}
__device__ __forceinline__ float lrelu(float v) { return v > 0.f ? v : ALPHA * v; }
__device__ __forceinline__ float sigm(float v) { return 1.f / (1.f + __expf(-v)); }
__device__ __forceinline__ float warp_sum(float v) {
#pragma unroll
    for (int o = 16; o > 0; o >>= 1) v += __shfl_xor_sync(0xffffffffu, v, o);
    return v;
}
__device__ __forceinline__ float warp_max(float v) {
#pragma unroll
    for (int o = 16; o > 0; o >>= 1) v = fmaxf(v, __shfl_xor_sync(0xffffffffu, v, o));
    return v;
}

// ---- smem layout: no overlapping lifetimes except Xh(XmT->h1). All bases %4==0 ----
#define OFF_XH    0         // 13420
#define OFF_FEATS 13420     // 13220 = 5*FHS
#define OFF_W1S   26640     // 13220
#define OFF_W2C   39860     // 1488 = 12*124
#define OFF_F2S   41348     // 1320
#define OFF_HP    42668     // 1320
#define OFF_ES1   43988     // 552
#define OFF_EN1   44540     // 560 = 5*ENS
#define OFF_ES2   45100     // 332
#define OFF_EN2   45432     // 336 = 3*ENS
#define OFF_AS1   45768     // 120
#define OFF_AN1   45888     // 120
#define OFF_B1    46008     // 24
#define OFF_AS2   46032     // 12
#define OFF_AN2   46044     // 12
#define OFF_B2    46056     // 4
#define OFF_FC1   46060     // 4
#define OFF_TS    46064     // 112
#define OFF_US    46176     // 112
#define OFF_AM    46288     // 440 uints
#define SMEM_FLOATS (OFF_AM + 440)
#define SMEM_BYTES (SMEM_FLOATS * 4)

__global__ __launch_bounds__(NT, 1)
void gatmil_kernel(const float* __restrict__ X, const float* __restrict__ A,
                   const float* __restrict__ M,
                   const float* __restrict__ W1, const float* __restrict__ as1,
                   const float* __restrict__ an1, const float* __restrict__ b1,
                   const float* __restrict__ W2, const float* __restrict__ as2,
                   const float* __restrict__ an2, const float* __restrict__ b2,
                   const float* __restrict__ fc1, const float* __restrict__ fc2,
                   float* __restrict__ out)
{
    extern __shared__ float sm[];
    float* Xh    = sm + OFF_XH;      // XmT (transposed) during P0-P1; h1 rows from P2 on
    float* feats = sm + OFF_FEATS;
    float* W1s   = sm + OFF_W1S;
    float* W2c   = sm + OFF_W2C;
    float* f2s   = sm + OFF_F2S;
    float* hp    = sm + OFF_HP;
    float* es1   = sm + OFF_ES1;
    float* en1   = sm + OFF_EN1;     // [h][ENS], pad zeroed
    float* es2   = sm + OFF_ES2;
    float* en2   = sm + OFF_EN2;     // [h2][ENS], pad zeroed
    float* as1s  = sm + OFF_AS1;
    float* an1s  = sm + OFF_AN1;
    float* b1s   = sm + OFF_B1;
    float* as2s  = sm + OFF_AS2;
    float* an2s  = sm + OFF_AN2;
    float* b2s   = sm + OFF_B2;
    float* fc1s  = sm + OFF_FC1;
    float* ts    = sm + OFF_TS;
    float* us    = sm + OFF_US;
    unsigned* Amask = (unsigned*)(sm + OFF_AM);

    const int b = blockIdx.x;
    const int tid = threadIdx.x;
    const int lane = tid & 31;
    const int wid = tid >> 5;

    const float* Xb = X + (size_t)b * NN * NN;
    const float* Ab = A + (size_t)b * NN * NN;

    // ================= P0: stage =================
    for (int h = 0; h < 5; h++)
        for (int j = tid; j < 2640; j += NT)
            W1s[h * FHS + j] = W1[h * 2640 + j];
    for (int i = tid; i < 120; i += NT) { as1s[i] = as1[i]; an1s[i] = an1[i]; }
    if (tid < 24) b1s[tid] = b1[tid];
    for (int idx = tid; idx < 12 * 124; idx += NT) {
        int c = idx / 124, k = idx - c * 124;
        int h2 = c >> 2, f2 = c & 3;
        float v = 0.f;
        if (k < 120 && f2 < 3) v = W2[(h2 * 120 + k) * 3 + f2];
        W2c[idx] = v;
    }
    if (tid < 9) { as2s[tid] = as2[tid]; an2s[tid] = an2[tid]; }
    if (tid < 3) { b2s[tid] = b2[tid]; fc1s[tid] = fc1[tid]; }
    // pad slots of en1/en2 (finite values; masked out anyway)
    if (tid < 10) en1[(tid >> 1) * ENS + NN + (tid & 1)] = 0.f;
    else if (tid < 16) en2[((tid - 10) >> 1) * ENS + NN + (tid & 1)] = 0.f;
    // XmT[i][n] = X[n][i] * sigmoid(M[n][i])  (coalesced read, strided smem write)
    for (int n = wid; n < NN; n += NT / 32)
        for (int i = lane; i < NN; i += 32)
            Xh[i * XS + n] = Xb[n * NN + i] * sigm(M[n * NN + i]);
    for (int w = wid; w < NN * 4; w += NT / 32) {
        int n = w >> 2, seg = w & 3;
        int m = seg * 32 + lane;
        float a = (m < NN) ? Ab[n * NN + m] : 0.f;
        unsigned bal = __ballot_sync(0xffffffffu, a > 0.f);
        if (lane == 0) Amask[w] = bal;
    }
    __syncthreads();

    // ========== P1: feats = Xm @ W1, row-per-thread (550 thr) + fused logits ==========
    if (tid < 550) {
        const int h = tid / NN, n = tid - h * NN;
        const float* wb = W1s + h * FHS;
        const float* xcol = Xh + n;          // XmT column n
        u64 acc[12];
#pragma unroll
        for (int j = 0; j < 12; j++) acc[j] = 0ull;
#pragma unroll 2
        for (int i = 0; i < NN; i++) {
            u64 s = splat2(xcol[i * XS]);
            const ulonglong2* w = (const ulonglong2*)(wb + i * 24);
            ulonglong2 w0 = w[0], w1 = w[1], w2 = w[2], w3 = w[3], w4 = w[4], w5 = w[5];
            acc[0]  = ffma2(s, w0.x, acc[0]);  acc[1]  = ffma2(s, w0.y, acc[1]);
            acc[2]  = ffma2(s, w1.x, acc[2]);  acc[3]  = ffma2(s, w1.y, acc[3]);
            acc[4]  = ffma2(s, w2.x, acc[4]);  acc[5]  = ffma2(s, w2.y, acc[5]);
            acc[6]  = ffma2(s, w3.x, acc[6]);  acc[7]  = ffma2(s, w3.y, acc[7]);
            acc[8]  = ffma2(s, w4.x, acc[8]);  acc[9]  = ffma2(s, w4.y, acc[9]);
            acc[10] = ffma2(s, w5.x, acc[10]); acc[11] = ffma2(s, w5.y, acc[11]);
        }
        u64* frow = (u64*)(feats + h * FHS + n * 24);
#pragma unroll
        for (int j = 0; j < 12; j++) frow[j] = acc[j];
        // fused logits from register-resident feats row
        const u64* ap = (const u64*)(as1s + h * 24);
        const u64* np = (const u64*)(an1s + h * 24);
        u64 sa = 0ull, sb = 0ull;
#pragma unroll
        for (int j = 0; j < 12; j++) {
            sa = ffma2(acc[j], ap[j], sa);
            sb = ffma2(acc[j], np[j], sb);
        }
        float2 fa = unpack2(sa), fb2 = unpack2(sb);
        es1[tid] = fa.x + fa.y;
        en1[h * ENS + n] = fb2.x + fb2.y;
    }
    __syncthreads();

    // ========== P2: fused softmax + aggregation, 4-way exp batching ==========
    if (tid < 550) {
        const int h = tid / NN, n = tid - h * NN;
        const float es = es1[tid];
        const float4* en4 = (const float4*)(en1 + h * ENS);
        const float* fbase = feats + h * FHS;
        unsigned mwr[4];
#pragma unroll
        for (int k = 0; k < 4; k++) mwr[k] = Amask[n * 4 + k];
        u64 acc[12];
#pragma unroll
        for (int j = 0; j < 12; j++) acc[j] = 0ull;
        float sum = 0.f;
#pragma unroll 2
        for (int m4 = 0; m4 < 28; m4++) {
            float4 ev = en4[m4];
            const unsigned mw = mwr[m4 >> 3];
            const int sh = (m4 & 7) * 4;
            float v0 = es + ev.x; v0 = v0 > 0.f ? v0 : ALPHA * v0;
            float v1 = es + ev.y; v1 = v1 > 0.f ? v1 : ALPHA * v1;
            float v2 = es + ev.z; v2 = v2 > 0.f ? v2 : ALPHA * v2;
            float v3 = es + ev.w; v3 = v3 > 0.f ? v3 : ALPHA * v3;
            float e0 = __expf(v0); e0 = ((mw >> sh) & 1u) ? e0 : 0.f;
            float e1 = __expf(v1); e1 = ((mw >> (sh + 1)) & 1u) ? e1 : 0.f;
            float e2 = __expf(v2); e2 = ((mw >> (sh + 2)) & 1u) ? e2 : 0.f;
            float e3 = __expf(v3); e3 = ((mw >> (sh + 3)) & 1u) ? e3 : 0.f;
            sum += (e0 + e1) + (e2 + e3);
            float ee[4] = {e0, e1, e2, e3};
#pragma unroll
            for (int j = 0; j < 4; j++) {
                u64 s = splat2(ee[j]);
                const ulonglong2* w = (const ulonglong2*)(fbase + (4 * m4 + j) * 24);
                ulonglong2 w0 = w[0], w1 = w[1], w2 = w[2], w3 = w[3], w4 = w[4], w5 = w[5];
                acc[0]  = ffma2(s, w0.x, acc[0]);  acc[1]  = ffma2(s, w0.y, acc[1]);
                acc[2]  = ffma2(s, w1.x, acc[2]);  acc[3]  = ffma2(s, w1.y, acc[3]);
                acc[4]  = ffma2(s, w2.x, acc[4]);  acc[5]  = ffma2(s, w2.y, acc[5]);
                acc[6]  = ffma2(s, w3.x, acc[6]);  acc[7]  = ffma2(s, w3.y, acc[7]);
                acc[8]  = ffma2(s, w4.x, acc[8]);  acc[9]  = ffma2(s, w4.y, acc[9]);
                acc[10] = ffma2(s, w5.x, acc[10]); acc[11] = ffma2(s, w5.y, acc[11]);
            }
        }
        const float rinv = 1.f / sum;
        float* dst = Xh + n * XS + h * 24;   // h1 row n (XmT dead)
        // b1 shape [24], shared across heads
#pragma unroll
        for (int j = 0; j < 12; j++) {
            float2 p = unpack2(acc[j]);
            p.x = lrelu(fmaf(p.x, rinv, b1s[2 * j]));
            p.y = lrelu(fmaf(p.y, rinv, b1s[2 * j + 1]));
            *(float2*)(dst + 2 * j) = p;
        }
    }
    __syncthreads();

    // ================= P3: f2s = h1 @ W2 =================
    for (int idx = tid; idx < NN * 12; idx += NT) {
        int n = idx / 12, c = idx - n * 12;
        const u64* xr = (const u64*)(Xh + n * XS);
        const ulonglong2* wr = (const ulonglong2*)(W2c + c * 124);
        u64 acc0 = 0ull, acc1 = 0ull;
#pragma unroll 5
        for (int j = 0; j < 60; j += 2) {
            ulonglong2 wv = wr[j >> 1];
            acc0 = ffma2(xr[j], wv.x, acc0);
            acc1 = ffma2(xr[j + 1], wv.y, acc1);
        }
        float2 v0 = unpack2(acc0), v1 = unpack2(acc1);
        f2s[(c >> 2) * (NN * 4) + n * 4 + (c & 3)] = (v0.x + v0.y) + (v1.x + v1.y);
    }
    __syncthreads();

    // ================= P3b: layer-2 logit halves =================
    if (tid < 330) {
        int h2 = tid / NN, n = tid - h2 * NN;
        float4 fv = *(const float4*)(f2s + tid * 4);
        es2[tid] = fv.x * as2s[h2 * 3] + fv.y * as2s[h2 * 3 + 1] + fv.z * as2s[h2 * 3 + 2];
        en2[h2 * ENS + n] = fv.x * an2s[h2 * 3] + fv.y * an2s[h2 * 3 + 1] + fv.z * an2s[h2 * 3 + 2];
    }
    __syncthreads();

    // ========== P4: fused layer-2 softmax + aggregation, 4-way batching ==========
    if (tid < 330) {
        const int h2 = tid / NN, n = tid - h2 * NN;
        const float es = es2[tid];
        const float4* en4 = (const float4*)(en2 + h2 * ENS);
        const ulonglong2* fbw = (const ulonglong2*)(f2s + h2 * (NN * 4));
        unsigned mwr[4];
#pragma unroll
        for (int k = 0; k < 4; k++) mwr[k] = Amask[n * 4 + k];
        u64 a0 = 0ull, a1 = 0ull;
        float sum = 0.f;
#pragma unroll 2
        for (int m4 = 0; m4 < 28; m4++) {
            float4 ev = en4[m4];
            const unsigned mw = mwr[m4 >> 3];
            const int sh = (m4 & 7) * 4;
            float v0 = es + ev.x; v0 = v0 > 0.f ? v0 : ALPHA * v0;
            float v1 = es + ev.y; v1 = v1 > 0.f ? v1 : ALPHA * v1;
            float v2 = es + ev.z; v2 = v2 > 0.f ? v2 : ALPHA * v2;
            float v3 = es + ev.w; v3 = v3 > 0.f ? v3 : ALPHA * v3;
            float e0 = __expf(v0); e0 = ((mw >> sh) & 1u) ? e0 : 0.f;
            float e1 = __expf(v1); e1 = ((mw >> (sh + 1)) & 1u) ? e1 : 0.f;
            float e2 = __expf(v2); e2 = ((mw >> (sh + 2)) & 1u) ? e2 : 0.f;
            float e3 = __expf(v3); e3 = ((mw >> (sh + 3)) & 1u) ? e3 : 0.f;
            sum += (e0 + e1) + (e2 + e3);
            float ee[4] = {e0, e1, e2, e3};
#pragma unroll
            for (int j = 0; j < 4; j++) {
                u64 s = splat2(ee[j]);
                ulonglong2 w = fbw[4 * m4 + j];
                a0 = ffma2(s, w.x, a0);
                a1 = ffma2(s, w.y, a1);
            }
        }
        const float rinv = 1.f / sum;
        float2 v0 = unpack2(a0), v1 = unpack2(a1);
        float4 o; o.x = v0.x * rinv; o.y = v0.y * rinv; o.z = v1.x * rinv; o.w = 0.f;
        *(float4*)(hp + tid * 4) = o;
    }
    __syncthreads();

    // ================= P5: node probs =================
    if (tid < NN) {
        float4 p0 = *(const float4*)(hp + tid * 4);
        float4 p1 = *(const float4*)(hp + (NN + tid) * 4);
        float4 p2 = *(const float4*)(hp + (2 * NN + tid) * 4);
        float z = lrelu(fmaf((p0.x + p1.x + p2.x), (1.f / 3.f), b2s[0])) * fc1s[0]
                + lrelu(fmaf((p0.y + p1.y + p2.y), (1.f / 3.f), b2s[1])) * fc1s[1]
                + lrelu(fmaf((p0.z + p1.z + p2.z), (1.f / 3.f), b2s[2])) * fc1s[2];
        ts[tid] = sigm(z);
    }
    __syncthreads();

    // ================= P6: MIL pooling =================
    if (tid < 448) {
        int m = tid >> 2, q = tid & 3;
        float s = 0.f;
        if (m < NN) {
            int n0 = q * 28, n1 = n0 + 28 < NN ? n0 + 28 : NN;
            for (int n = n0; n < n1; n++) s = fmaf(ts[n], fc2[n * NN + m], s);
        }
        s += __shfl_xor_sync(0xffffffffu, s, 1);
        s += __shfl_xor_sync(0xffffffffu, s, 2);
        if (q == 0 && m < NN) us[m] = s;
    }
    __syncthreads();
    if (wid == 0) {
        float vmax = -3.4e38f;
        for (int m = lane; m < NN; m += 32) vmax = fmaxf(vmax, us[m]);
        vmax = warp_max(vmax);
        float num = 0.f, den = 0.f;
        for (int m = lane; m < NN; m += 32) {
            float e = __expf(us[m] - vmax);
            num = fmaf(ts[m], e, num);
            den += e;
        }
        num = warp_sum(num);
        den = warp_sum(den);
        if (lane == 0) out[b] = num / den;
    }
}

extern "C" void kernel_launch(void* const* d_in, const int* in_sizes, int n_in,
                              void* d_out, int out_size)
{
    const float* X   = (const float*)d_in[0];
    const float* A   = (const float*)d_in[1];
    const float* M   = (const float*)d_in[2];
    const float* W1  = (const float*)d_in[3];
    const float* as1 = (const float*)d_in[4];
    const float* an1 = (const float*)d_in[5];
    const float* b1  = (const float*)d_in[6];
    const float* W2  = (const float*)d_in[7];
    const float* as2 = (const float*)d_in[8];
    const float* an2 = (const float*)d_in[9];
    const float* b2  = (const float*)d_in[10];
    const float* fc1 = (const float*)d_in[11];
    const float* fc2 = (const float*)d_in[12];
    float* out = (float*)d_out;

    const int B = in_sizes[0] / (NN * NN);

    cudaFuncSetAttribute(gatmil_kernel, cudaFuncAttributeMaxDynamicSharedMemorySize, SMEM_BYTES);
    gatmil_kernel<<<B, NT, SMEM_BYTES>>>(X, A, M, W1, as1, an1, b1,
                                         W2, as2, an2, b2, fc1, fc2, out);
}